// round 11
// baseline (speedup 1.0000x reference)
#include <cuda_runtime.h>
#include <cuda_fp16.h>
#include <math.h>

#define NB   16            // batches
#define NN   1024          // N == Mp
#define GRID 128           // 16 batches x 8 blocks; 1 CTA/SM, all co-resident
#define TPB  256
#define PB   8             // blocks per batch
#define RPW  16            // rows per warp
#define CROWS 9            // rows/warp L1-resident (default ld); rest __ldcg

// ---- static device scratch (no allocations allowed) ----
__device__ uint4  g_K4[(size_t)NB * NN * NN / 8];   // fp16 K' = 4096*exp(-C/eps)
__device__ float  g_part[2][NB][PB][NN];
__device__ float  g_errpart[2][GRID];
__device__ float  g_costpart[GRID];
__device__ int          g_cnt;
__device__ volatile int g_gen;

// ---- software grid barrier (128 blocks, 1/SM, guaranteed resident) ----
__device__ __forceinline__ void gridbar() {
    __syncthreads();
    if (threadIdx.x == 0) {
        __threadfence();
        int g = g_gen;
        if (atomicAdd(&g_cnt, 1) == GRID - 1) {
            g_cnt = 0;
            __threadfence();
            g_gen = g + 1;
        } else {
            while (g_gen == g) __nanosleep(32);
        }
        __threadfence();
    }
    __syncthreads();
}

__device__ __forceinline__ void h8_to_f8(const uint4 v, float* f) {
    float2 a = __half22float2(*(const __half2*)&v.x);
    float2 b = __half22float2(*(const __half2*)&v.y);
    float2 c = __half22float2(*(const __half2*)&v.z);
    float2 d = __half22float2(*(const __half2*)&v.w);
    f[0]=a.x; f[1]=a.y; f[2]=b.x; f[3]=b.y; f[4]=c.x; f[5]=c.y; f[6]=d.x; f[7]=d.y;
}

__global__ void __launch_bounds__(TPB, 1)
k_sinkhorn(const float* __restrict__ C, float* __restrict__ out)
{
    __shared__ float sT[8][NN];      // 32 KB: per-warp column partials
    __shared__ float sb[NN];         // current b (exp(v/eps)) for this batch
    __shared__ float sU[128];
    __shared__ float sA[128];
    __shared__ float sred[TPB];

    const int bid = blockIdx.x;
    const int b   = bid >> 3;
    const int ib  = bid & 7;
    const int tid = threadIdx.x;
    const int w   = tid >> 5;
    const int l   = tid & 31;
    const int rowBase = (b << 10) + (ib << 7);   // 128 rows per block
    const int wrow    = rowBase + w * RPW;       // this warp's 16 rows

    const float MUA = (1.0f / 1024.0f + 1e-8f) * 4096.0f;  // mu * 4096
    const float UC  = logf(MUA);
    const float KSH = 8.317766166719343f;                  // 12 ln2

    if (tid < 128) { sU[tid] = 0.f; sA[tid] = 0.f; }
    ((float4*)sb)[tid] = make_float4(1.f, 1.f, 1.f, 1.f);  // b0 = 1
    __syncthreads();

    const float4* C4      = (const float4*)C;
    float*        outCost = out;
    float4*       outPi   = (float4*)(out + NB);
    float4*       outC    = (float4*)(out + NB + (size_t)NB * NN * NN);

    int par = 0;
    for (int t = 0; t < 100; t++) {
        // ---- cache b in registers: lane covers cols (k*32+l)*8 + e ----
        float bb[4][8];
        #pragma unroll
        for (int k = 0; k < 4; k++) {
            float4 p0 = ((const float4*)sb)[(((k << 5) + l) << 1)];
            float4 p1 = ((const float4*)sb)[(((k << 5) + l) << 1) + 1];
            bb[k][0]=p0.x; bb[k][1]=p0.y; bb[k][2]=p0.z; bb[k][3]=p0.w;
            bb[k][4]=p1.x; bb[k][5]=p1.y; bb[k][6]=p1.z; bb[k][7]=p1.w;
        }
        float Tacc[4][8];
        #pragma unroll
        for (int k = 0; k < 4; k++)
            #pragma unroll
            for (int e = 0; e < 8; e++) Tacc[k][e] = 0.f;
        float du = 0.f;

        // per-row worker: plain fp32 dot, u/a update, T accumulate (R8 proven)
        auto proc = [&](float kf[4][8], int r) {
            float s = 0.f;
            #pragma unroll
            for (int k = 0; k < 4; k++)
                #pragma unroll
                for (int e = 0; e < 8; e++) s = fmaf(kf[k][e], bb[k][e], s);
            #pragma unroll
            for (int o = 16; o; o >>= 1) s += __shfl_xor_sync(~0u, s, o);
            float a = MUA / s;
            if (l == 0) {
                float un = 0.1f * (UC - logf(s));
                int ri = w * RPW + r;
                du += fabsf(un - sU[ri]);
                sU[ri] = un; sA[ri] = a;
            }
            #pragma unroll
            for (int k = 0; k < 4; k++)
                #pragma unroll
                for (int e = 0; e < 8; e++)
                    Tacc[k][e] = fmaf(a, kf[k][e], Tacc[k][e]);
        };

        if (t == 0) {
            // ---- first pass: build fp16 K', stream outC passthrough ----
            for (int r = 0; r < RPW; r++) {
                int row = wrow + r;
                float kf[4][8];
                #pragma unroll
                for (int k = 0; k < 4; k++) {
                    size_t q = (size_t)row * 256 + (((k << 5) + l) << 1);
                    float4 c0 = __ldcs(C4 + q);
                    float4 c1 = __ldcs(C4 + q + 1);
                    __stcs(outC + q,     c0);     // C passthrough, fire & forget
                    __stcs(outC + q + 1, c1);
                    __half2 h0 = __floats2half2_rn(__expf(fmaf(-10.f, c0.x, KSH)),
                                                   __expf(fmaf(-10.f, c0.y, KSH)));
                    __half2 h1 = __floats2half2_rn(__expf(fmaf(-10.f, c0.z, KSH)),
                                                   __expf(fmaf(-10.f, c0.w, KSH)));
                    __half2 h2 = __floats2half2_rn(__expf(fmaf(-10.f, c1.x, KSH)),
                                                   __expf(fmaf(-10.f, c1.y, KSH)));
                    __half2 h3 = __floats2half2_rn(__expf(fmaf(-10.f, c1.z, KSH)),
                                                   __expf(fmaf(-10.f, c1.w, KSH)));
                    uint4 v;
                    v.x = *(unsigned*)&h0; v.y = *(unsigned*)&h1;
                    v.z = *(unsigned*)&h2; v.w = *(unsigned*)&h3;
                    __stcg(&g_K4[(size_t)row * 128 + (k << 5) + l], v);
                    // use fp16-rounded values so iterations are consistent
                    uint4 vv = v;
                    h8_to_f8(vv, kf[k]);
                }
                proc(kf, r);
            }
        } else {
            // ---- steady state: R8-style prefetch, L1-cached/bypass split ----
            uint4 kq[4];
            {
                size_t gq = (size_t)wrow * 128;
                #pragma unroll
                for (int k = 0; k < 4; k++) kq[k] = g_K4[gq + (k << 5) + l];
            }
            for (int r = 0; r < RPW; r++) {
                uint4 kn[4];
                if (r + 1 < RPW) {
                    size_t gq = (size_t)(wrow + r + 1) * 128;
                    if (r + 1 < CROWS) {
                        #pragma unroll
                        for (int k = 0; k < 4; k++)
                            kn[k] = g_K4[gq + (k << 5) + l];          // L1 set
                    } else {
                        #pragma unroll
                        for (int k = 0; k < 4; k++)
                            kn[k] = __ldcg(&g_K4[gq + (k << 5) + l]); // bypass
                    }
                }
                float kf[4][8];
                #pragma unroll
                for (int k = 0; k < 4; k++) h8_to_f8(kq[k], kf[k]);
                proc(kf, r);
                if (r + 1 < RPW) {
                    #pragma unroll
                    for (int k = 0; k < 4; k++) kq[k] = kn[k];
                }
            }
        }

        // ---- block-combine 8 warps' column partials (deterministic) ----
        {
            float4* me = (float4*)sT[w];
            #pragma unroll
            for (int k = 0; k < 4; k++) {
                int q = (k << 5) + l;
                me[2 * q]     = make_float4(Tacc[k][0], Tacc[k][1], Tacc[k][2], Tacc[k][3]);
                me[2 * q + 1] = make_float4(Tacc[k][4], Tacc[k][5], Tacc[k][6], Tacc[k][7]);
            }
            if (l == 0) sred[w] = du;
        }
        __syncthreads();
        {
            float4 Tj = ((const float4*)sT[0])[tid];
            #pragma unroll
            for (int ww = 1; ww < 8; ww++) {
                float4 x = ((const float4*)sT[ww])[tid];
                Tj.x += x.x; Tj.y += x.y; Tj.z += x.z; Tj.w += x.w;
            }
            ((float4*)g_part[par][b][ib])[tid] = Tj;
        }
        if (tid == 0) {
            float e = 0.f;
            #pragma unroll
            for (int ww = 0; ww < 8; ww++) e += sred[ww];
            g_errpart[par][bid] = e;
        }

        gridbar();

        // ---- v update: combine 8 block partials (redundant per block) ----
        float4 T = make_float4(0.f, 0.f, 0.f, 0.f);
        #pragma unroll
        for (int kk = 0; kk < PB; kk++) {
            float4 x = __ldcg(((const float4*)g_part[par][b][kk]) + tid);
            T.x += x.x; T.y += x.y; T.z += x.z; T.w += x.w;
        }
        float4 bbn;
        bbn.x = MUA / T.x; bbn.y = MUA / T.y; bbn.z = MUA / T.z; bbn.w = MUA / T.w;

        // deterministic err reduction
        sred[tid] = (tid < GRID) ? __ldcg(&g_errpart[par][tid]) : 0.f;
        __syncthreads();
        for (int o = 128; o; o >>= 1) {
            if (tid < o) sred[tid] += sred[tid + o];
            __syncthreads();
        }
        float err = sred[0];

        ((float4*)sb)[tid] = bbn;
        __syncthreads();

        if (err < 0.1f * (float)NB) break;   // err/B < THRESH
        par ^= 1;
    }

    // ---- epilogue: pi = a*b*K'/4096, cost via C reconstructed from K' ----
    float bbf[4][8];
    #pragma unroll
    for (int k = 0; k < 4; k++) {
        float4 p0 = ((const float4*)sb)[(((k << 5) + l) << 1)];
        float4 p1 = ((const float4*)sb)[(((k << 5) + l) << 1) + 1];
        bbf[k][0]=p0.x; bbf[k][1]=p0.y; bbf[k][2]=p0.z; bbf[k][3]=p0.w;
        bbf[k][4]=p1.x; bbf[k][5]=p1.y; bbf[k][6]=p1.z; bbf[k][7]=p1.w;
    }
    const float LN2E = 0.069314718f;   // 0.1 * ln2
    const float CC   = 0.8317766167f;  // 0.1 * 12 ln2
    float cost = 0.f;

    for (int r = 0; r < RPW; r++) {
        int row = wrow + r;
        float ap = sA[w * RPW + r] * (1.0f / 4096.0f);
        float kf[4][8];
        size_t gq = (size_t)row * 128;
        if (r < CROWS) {
            #pragma unroll
            for (int k = 0; k < 4; k++) {
                uint4 v = g_K4[gq + (k << 5) + l];           // L1 hits from loop
                h8_to_f8(v, kf[k]);
            }
        } else {
            #pragma unroll
            for (int k = 0; k < 4; k++) {
                uint4 v = __ldcg(&g_K4[gq + (k << 5) + l]);
                h8_to_f8(v, kf[k]);
            }
        }
        #pragma unroll
        for (int k = 0; k < 4; k++) {
            int q = (k << 5) + l;
            float p[8];
            #pragma unroll
            for (int e = 0; e < 8; e++) p[e] = ap * kf[k][e] * bbf[k][e];
            __stcs(&outPi[(size_t)row * 256 + 2 * q],
                   make_float4(p[0], p[1], p[2], p[3]));
            __stcs(&outPi[(size_t)row * 256 + 2 * q + 1],
                   make_float4(p[4], p[5], p[6], p[7]));
            #pragma unroll
            for (int e = 0; e < 8; e++) {
                float c = fmaf(-LN2E, __log2f(kf[k][e]), CC);
                cost = fmaf(p[e], c, cost);
            }
        }
    }
    __syncthreads();
    sred[tid] = cost;
    __syncthreads();
    for (int o = 128; o; o >>= 1) {
        if (tid < o) sred[tid] += sred[tid + o];
        __syncthreads();
    }
    if (tid == 0) g_costpart[bid] = sred[0];

    gridbar();

    if (bid == 0 && tid < NB) {               // deterministic final cost sum
        float cs = 0.f;
        #pragma unroll
        for (int kk = 0; kk < PB; kk++)
            cs += __ldcg(&g_costpart[(tid << 3) + kk]);
        outCost[tid] = cs;
    }
}

// ---------------- launch -----------------------------------------------------
extern "C" void kernel_launch(void* const* d_in, const int* in_sizes, int n_in,
                              void* d_out, int out_size) {
    const float* C = nullptr;
    for (int i = 0; i < n_in; i++)
        if (in_sizes[i] == NB * NN * NN) C = (const float*)d_in[i];
    k_sinkhorn<<<GRID, TPB>>>(C, (float*)d_out);
    (void)out_size;
}

// round 12
// speedup vs baseline: 1.0257x; 1.0257x over previous
#include <cuda_runtime.h>
#include <cuda_fp16.h>
#include <math.h>

#define NB   16            // batches
#define NN   1024          // N == Mp
#define GRID 128           // 16 batches x 8 blocks; 1 CTA/SM, all co-resident
#define TPB  512           // 16 warps/SM (R12: occupancy doubling)
#define NW   16            // warps per block
#define PB   8             // blocks per batch
#define RPW  8             // rows per warp (16 warps x 8 = 128 rows/block)

// ---- dynamic smem layout (bytes) ----
#define OFF_ST   0
#define SZ_ST    (NW * NN * 4)          // 65536: per-warp column partials
#define OFF_SB   (OFF_ST + SZ_ST)
#define SZ_SB    (NN * 4)               // 4096: b vector
#define OFF_SU   (OFF_SB + SZ_SB)       // 512: u (128 rows)
#define OFF_SA   (OFF_SU + 512)         // 512: a
#define OFF_SR   (OFF_SA + 512)         // 2048: reduction (512 threads)
#define SMEM_TOTAL (OFF_SR + 2048)      // 72704

// ---- static device scratch (no allocations allowed) ----
__device__ uint4  g_K4[(size_t)NB * NN * NN / 8];   // fp16 K' = 4096*exp(-C/eps)
__device__ float  g_part[2][NB][PB][NN];
__device__ float  g_errpart[2][GRID];
__device__ float  g_costpart[GRID];
__device__ int          g_cnt;
__device__ volatile int g_gen;

// ---- software grid barrier (128 blocks, 1/SM, guaranteed resident) ----
__device__ __forceinline__ void gridbar() {
    __syncthreads();
    if (threadIdx.x == 0) {
        __threadfence();
        int g = g_gen;
        if (atomicAdd(&g_cnt, 1) == GRID - 1) {
            g_cnt = 0;
            __threadfence();
            g_gen = g + 1;
        } else {
            while (g_gen == g) __nanosleep(32);
        }
        __threadfence();
    }
    __syncthreads();
}

__device__ __forceinline__ void h8_to_f8(const uint4 v, float* f) {
    float2 a = __half22float2(*(const __half2*)&v.x);
    float2 b = __half22float2(*(const __half2*)&v.y);
    float2 c = __half22float2(*(const __half2*)&v.z);
    float2 d = __half22float2(*(const __half2*)&v.w);
    f[0]=a.x; f[1]=a.y; f[2]=b.x; f[3]=b.y; f[4]=c.x; f[5]=c.y; f[6]=d.x; f[7]=d.y;
}

__global__ void __launch_bounds__(TPB, 1)
k_sinkhorn(const float* __restrict__ C, float* __restrict__ out)
{
    extern __shared__ unsigned char smraw[];
    float* sT   = (float*)(smraw + OFF_ST);     // [NW][NN]
    float* sb   = (float*)(smraw + OFF_SB);
    float* sU   = (float*)(smraw + OFF_SU);
    float* sA   = (float*)(smraw + OFF_SA);
    float* sred = (float*)(smraw + OFF_SR);

    const int bid = blockIdx.x;
    const int b   = bid >> 3;
    const int ib  = bid & 7;
    const int tid = threadIdx.x;
    const int w   = tid >> 5;            // warp 0..15
    const int l   = tid & 31;
    const int rowBase = (b << 10) + (ib << 7);   // 128 rows per block
    const int wrow    = rowBase + w * RPW;       // this warp's 8 rows

    const float MUA = (1.0f / 1024.0f + 1e-8f) * 4096.0f;  // mu * 4096
    const float UC  = logf(MUA);
    const float KSH = 8.317766166719343f;                  // 12 ln2

    if (tid < 128) { sU[tid] = 0.f; sA[tid] = 0.f; }
    ((float2*)sb)[tid] = make_float2(1.f, 1.f);            // b0 = 1
    __syncthreads();

    const float4* C4      = (const float4*)C;
    float*        outCost = out;
    float4*       outPi   = (float4*)(out + NB);
    float4*       outC    = (float4*)(out + NB + (size_t)NB * NN * NN);

    int par = 0;
    for (int t = 0; t < 100; t++) {
        // ---- cache b in registers: lane covers cols (k*32+l)*8 + e ----
        float bb[4][8];
        #pragma unroll
        for (int k = 0; k < 4; k++) {
            float4 p0 = ((const float4*)sb)[(((k << 5) + l) << 1)];
            float4 p1 = ((const float4*)sb)[(((k << 5) + l) << 1) + 1];
            bb[k][0]=p0.x; bb[k][1]=p0.y; bb[k][2]=p0.z; bb[k][3]=p0.w;
            bb[k][4]=p1.x; bb[k][5]=p1.y; bb[k][6]=p1.z; bb[k][7]=p1.w;
        }
        float Tacc[4][8];
        #pragma unroll
        for (int k = 0; k < 4; k++)
            #pragma unroll
            for (int e = 0; e < 8; e++) Tacc[k][e] = 0.f;
        float du = 0.f;

        // per-row worker: group-wise unpack (8 floats live) keeps regs <=128
        auto proc = [&](const uint4* kq, int r) {
            float s = 0.f;
            #pragma unroll
            for (int k = 0; k < 4; k++) {
                float kf[8];
                h8_to_f8(kq[k], kf);
                #pragma unroll
                for (int e = 0; e < 8; e++) s = fmaf(kf[e], bb[k][e], s);
            }
            #pragma unroll
            for (int o = 16; o; o >>= 1) s += __shfl_xor_sync(~0u, s, o);
            float a = MUA / s;
            if (l == 0) {
                float un = 0.1f * (UC - logf(s));
                int ri = w * RPW + r;
                du += fabsf(un - sU[ri]);
                sU[ri] = un; sA[ri] = a;
            }
            #pragma unroll
            for (int k = 0; k < 4; k++) {
                float kf[8];
                h8_to_f8(kq[k], kf);
                #pragma unroll
                for (int e = 0; e < 8; e++)
                    Tacc[k][e] = fmaf(a, kf[e], Tacc[k][e]);
            }
        };

        if (t == 0) {
            // ---- first pass: build fp16 K' from C ----
            #pragma unroll
            for (int r = 0; r < RPW; r++) {
                int row = wrow + r;
                uint4 kv[4];
                #pragma unroll
                for (int k = 0; k < 4; k++) {
                    size_t q = (size_t)row * 256 + (((k << 5) + l) << 1);
                    float4 c0 = C4[q];
                    float4 c1 = C4[q + 1];
                    __half2 h0 = __floats2half2_rn(__expf(fmaf(-10.f, c0.x, KSH)),
                                                   __expf(fmaf(-10.f, c0.y, KSH)));
                    __half2 h1 = __floats2half2_rn(__expf(fmaf(-10.f, c0.z, KSH)),
                                                   __expf(fmaf(-10.f, c0.w, KSH)));
                    __half2 h2 = __floats2half2_rn(__expf(fmaf(-10.f, c1.x, KSH)),
                                                   __expf(fmaf(-10.f, c1.y, KSH)));
                    __half2 h3 = __floats2half2_rn(__expf(fmaf(-10.f, c1.z, KSH)),
                                                   __expf(fmaf(-10.f, c1.w, KSH)));
                    uint4 v;
                    v.x = *(unsigned*)&h0; v.y = *(unsigned*)&h1;
                    v.z = *(unsigned*)&h2; v.w = *(unsigned*)&h3;
                    g_K4[(size_t)row * 128 + (k << 5) + l] = v;
                    kv[k] = v;   // fp16-rounded so iterations are consistent
                }
                proc(kv, r);
            }
        } else {
            // ---- steady state: plain loads, rely on 16 warps for hiding ----
            #pragma unroll
            for (int r = 0; r < RPW; r++) {
                size_t gq = (size_t)(wrow + r) * 128;
                uint4 kq[4];
                #pragma unroll
                for (int k = 0; k < 4; k++) kq[k] = g_K4[gq + (k << 5) + l];
                proc(kq, r);
            }
        }

        // ---- block-combine 16 warps' column partials (deterministic) ----
        {
            float4* me = (float4*)(sT + w * NN);
            #pragma unroll
            for (int k = 0; k < 4; k++) {
                int q = (k << 5) + l;
                me[2 * q]     = make_float4(Tacc[k][0], Tacc[k][1], Tacc[k][2], Tacc[k][3]);
                me[2 * q + 1] = make_float4(Tacc[k][4], Tacc[k][5], Tacc[k][6], Tacc[k][7]);
            }
            if (l == 0) sred[w] = du;
        }
        __syncthreads();
        {
            // 512 threads x float2 = 1024 floats
            float2 Tj = ((const float2*)sT)[tid];
            #pragma unroll
            for (int ww = 1; ww < NW; ww++) {
                float2 x = ((const float2*)(sT + ww * NN))[tid];
                Tj.x += x.x; Tj.y += x.y;
            }
            ((float2*)g_part[par][b][ib])[tid] = Tj;
        }
        if (tid == 0) {
            float e = 0.f;
            #pragma unroll
            for (int ww = 0; ww < NW; ww++) e += sred[ww];
            g_errpart[par][bid] = e;
        }

        gridbar();

        // ---- v update: combine 8 block partials (redundant per block) ----
        float2 T = make_float2(0.f, 0.f);
        #pragma unroll
        for (int kk = 0; kk < PB; kk++) {
            float2 x = __ldcg(((const float2*)g_part[par][b][kk]) + tid);
            T.x += x.x; T.y += x.y;
        }
        float2 bbn;
        bbn.x = MUA / T.x; bbn.y = MUA / T.y;

        // deterministic err reduction (512 threads over 128 partials)
        sred[tid] = (tid < GRID) ? __ldcg(&g_errpart[par][tid]) : 0.f;
        __syncthreads();
        for (int o = 256; o; o >>= 1) {
            if (tid < o) sred[tid] += sred[tid + o];
            __syncthreads();
        }
        float err = sred[0];

        ((float2*)sb)[tid] = bbn;
        __syncthreads();

        if (err < 0.1f * (float)NB) break;   // err/B < THRESH
        par ^= 1;
    }

    // ---- epilogue (R8-style): read C, pi = a*b*exp(-C/eps), outC, cost ----
    float bbf[4][8];
    #pragma unroll
    for (int k = 0; k < 4; k++) {
        float4 p0 = ((const float4*)sb)[(((k << 5) + l) << 1)];
        float4 p1 = ((const float4*)sb)[(((k << 5) + l) << 1) + 1];
        bbf[k][0]=p0.x; bbf[k][1]=p0.y; bbf[k][2]=p0.z; bbf[k][3]=p0.w;
        bbf[k][4]=p1.x; bbf[k][5]=p1.y; bbf[k][6]=p1.z; bbf[k][7]=p1.w;
    }
    float cost = 0.f;

    for (int r = 0; r < RPW; r++) {
        int row = wrow + r;
        float ap = sA[w * RPW + r] * (1.0f / 4096.0f);
        #pragma unroll
        for (int k = 0; k < 4; k++) {
            size_t q = (size_t)row * 256 + (((k << 5) + l) << 1);
            float4 c0 = __ldcs(C4 + q);
            float4 c1 = __ldcs(C4 + q + 1);
            __stcs(outC + q,     c0);
            __stcs(outC + q + 1, c1);
            float p[8];
            p[0] = ap * bbf[k][0] * __expf(fmaf(-10.f, c0.x, KSH));
            p[1] = ap * bbf[k][1] * __expf(fmaf(-10.f, c0.y, KSH));
            p[2] = ap * bbf[k][2] * __expf(fmaf(-10.f, c0.z, KSH));
            p[3] = ap * bbf[k][3] * __expf(fmaf(-10.f, c0.w, KSH));
            p[4] = ap * bbf[k][4] * __expf(fmaf(-10.f, c1.x, KSH));
            p[5] = ap * bbf[k][5] * __expf(fmaf(-10.f, c1.y, KSH));
            p[6] = ap * bbf[k][6] * __expf(fmaf(-10.f, c1.z, KSH));
            p[7] = ap * bbf[k][7] * __expf(fmaf(-10.f, c1.w, KSH));
            __stcs(&outPi[q],     make_float4(p[0], p[1], p[2], p[3]));
            __stcs(&outPi[q + 1], make_float4(p[4], p[5], p[6], p[7]));
            cost = fmaf(p[0], c0.x, cost);
            cost = fmaf(p[1], c0.y, cost);
            cost = fmaf(p[2], c0.z, cost);
            cost = fmaf(p[3], c0.w, cost);
            cost = fmaf(p[4], c1.x, cost);
            cost = fmaf(p[5], c1.y, cost);
            cost = fmaf(p[6], c1.z, cost);
            cost = fmaf(p[7], c1.w, cost);
        }
    }
    __syncthreads();
    sred[tid] = cost;
    __syncthreads();
    for (int o = 256; o; o >>= 1) {
        if (tid < o) sred[tid] += sred[tid + o];
        __syncthreads();
    }
    if (tid == 0) g_costpart[bid] = sred[0];

    gridbar();

    if (bid == 0 && tid < NB) {               // deterministic final cost sum
        float cs = 0.f;
        #pragma unroll
        for (int kk = 0; kk < PB; kk++)
            cs += __ldcg(&g_costpart[(tid << 3) + kk]);
        outCost[tid] = cs;
    }
}

// ---------------- launch -----------------------------------------------------
extern "C" void kernel_launch(void* const* d_in, const int* in_sizes, int n_in,
                              void* d_out, int out_size) {
    const float* C = nullptr;
    for (int i = 0; i < n_in; i++)
        if (in_sizes[i] == NB * NN * NN) C = (const float*)d_in[i];
    cudaFuncSetAttribute(k_sinkhorn,
                         cudaFuncAttributeMaxDynamicSharedMemorySize, SMEM_TOTAL);
    k_sinkhorn<<<GRID, TPB, SMEM_TOTAL>>>(C, (float*)d_out);
    (void)out_size;
}

// round 13
// speedup vs baseline: 1.1373x; 1.1088x over previous
#include <cuda_runtime.h>
#include <cuda_fp16.h>
#include <math.h>

#define B   16
#define N   1024
#define MP  1024
#define EPS_F    0.1f
#define INV_EPS  10.0f
#define MAX_ITER 100
#define GRID 128            // 16 batches x 8 blocks; 1 CTA/SM, all co-resident
#define TPB  256
#define RPB  128            // rows per block
#define RPW  16             // rows per warp
#define PB   8              // blocks per batch

// ---------------- static device scratch (no allocations allowed) ------------
__device__ __half g_Kh[(size_t)B * N * MP];     // 32 MB: exp(-C/eps) in fp16
__device__ float  g_part[2][B][PB][MP];         // double-buffered column partials
__device__ float  g_errpart[2][GRID];
__device__ float  g_costpart[GRID];
__device__ int          g_cnt;
__device__ volatile int g_gen;

// -------- software grid barrier (128 blocks, 1/SM, guaranteed resident) -----
__device__ __forceinline__ void gridbar() {
    __syncthreads();
    if (threadIdx.x == 0) {
        __threadfence();
        int g = g_gen;
        if (atomicAdd(&g_cnt, 1) == GRID - 1) {
            g_cnt = 0;
            __threadfence();
            g_gen = g + 1;
        } else {
            while (g_gen == g) __nanosleep(64);
        }
        __threadfence();
    }
    __syncthreads();
}

__device__ __forceinline__ void h8_to_f8(const uint4 v, float* f) {
    float2 a = __half22float2(*(const __half2*)&v.x);
    float2 b = __half22float2(*(const __half2*)&v.y);
    float2 c = __half22float2(*(const __half2*)&v.z);
    float2 d = __half22float2(*(const __half2*)&v.w);
    f[0]=a.x; f[1]=a.y; f[2]=b.x; f[3]=b.y; f[4]=c.x; f[5]=c.y; f[6]=d.x; f[7]=d.y;
}

__global__ void __launch_bounds__(TPB, 1)
k_sinkhorn(const float* __restrict__ C, float* __restrict__ out)
{
    __shared__ float sb[MP];             // current b (exp(v/eps)) for this batch
    __shared__ float sT[8][MP];          // per-warp column partials
    __shared__ float sU[RPB];            // u values for this block's rows
    __shared__ float sA[RPB];            // a = exp(u/eps) for this block's rows
    __shared__ float sred[TPB];

    const int bid = blockIdx.x;
    const int b   = bid >> 3;            // batch 0..15
    const int ib  = bid & 7;             // block-in-batch 0..7
    const int tid = threadIdx.x;
    const int w   = tid >> 5;            // warp 0..7
    const int l   = tid & 31;
    const int rowBase = (b << 10) + (ib << 7);   // 128 rows per block
    const int wrow    = rowBase + w * RPW;       // this warp's 16 rows

    const float MU   = 1.0f / 1024.0f + 1e-8f;
    const float LOGM = logf(MU);

    // ---- per-replay init ----
    if (tid < RPB) { sU[tid] = 0.f; sA[tid] = 0.f; }
    ((float4*)sb)[tid] = make_float4(1.f, 1.f, 1.f, 1.f);   // b0 = 1
    __syncthreads();

    uint4*        K4 = (uint4*)g_Kh;     // 8 halfs/uint4, 128 uint4 per row
    const float4* C4 = (const float4*)C; // 256 float4 per row

    float*  outCost = out;
    float4* outPi   = (float4*)(out + B);
    float4* outC    = (float4*)(out + B + (size_t)B * N * MP);

    int par = 0, copied = 0;
    for (int t = 0; t < MAX_ITER; t++) {
        // -------- cache b in registers: lane covers cols (k*32+l)*8 + e -----
        float bb[4][8];
        #pragma unroll
        for (int k = 0; k < 4; k++) {
            float4 p0 = ((const float4*)sb)[(((k << 5) + l) << 1)];
            float4 p1 = ((const float4*)sb)[(((k << 5) + l) << 1) + 1];
            bb[k][0]=p0.x; bb[k][1]=p0.y; bb[k][2]=p0.z; bb[k][3]=p0.w;
            bb[k][4]=p1.x; bb[k][5]=p1.y; bb[k][6]=p1.z; bb[k][7]=p1.w;
        }
        float Tacc[4][8];
        #pragma unroll
        for (int k = 0; k < 4; k++)
            #pragma unroll
            for (int e = 0; e < 8; e++) Tacc[k][e] = 0.f;
        float du = 0.f;

        if (t == 0) {
            // ---- first pass: build fp16 K from C ----
            for (int r = 0; r < RPW; r++) {
                size_t qb = (size_t)(wrow + r) << 7;
                float kf[4][8];
                #pragma unroll
                for (int k = 0; k < 4; k++) {
                    size_t q = qb + (k << 5) + l;
                    float4 c0 = C4[q << 1];
                    float4 c1 = C4[(q << 1) + 1];
                    kf[k][0]=__expf(-c0.x*INV_EPS); kf[k][1]=__expf(-c0.y*INV_EPS);
                    kf[k][2]=__expf(-c0.z*INV_EPS); kf[k][3]=__expf(-c0.w*INV_EPS);
                    kf[k][4]=__expf(-c1.x*INV_EPS); kf[k][5]=__expf(-c1.y*INV_EPS);
                    kf[k][6]=__expf(-c1.z*INV_EPS); kf[k][7]=__expf(-c1.w*INV_EPS);
                    uint4 kv;
                    __half2 h;
                    h=__floats2half2_rn(kf[k][0],kf[k][1]); kv.x=*(unsigned*)&h;
                    h=__floats2half2_rn(kf[k][2],kf[k][3]); kv.y=*(unsigned*)&h;
                    h=__floats2half2_rn(kf[k][4],kf[k][5]); kv.z=*(unsigned*)&h;
                    h=__floats2half2_rn(kf[k][6],kf[k][7]); kv.w=*(unsigned*)&h;
                    K4[q] = kv;
                    // use the fp16-rounded values so iterations are consistent
                    h8_to_f8(kv, kf[k]);
                }
                float s = 0.f;
                #pragma unroll
                for (int k = 0; k < 4; k++)
                    #pragma unroll
                    for (int e = 0; e < 8; e++) s = fmaf(kf[k][e], bb[k][e], s);
                #pragma unroll
                for (int o = 16; o; o >>= 1) s += __shfl_xor_sync(~0u, s, o);
                float a = MU / s;
                if (l == 0) {
                    float unew = EPS_F * (LOGM - logf(s));
                    int ri = w * RPW + r;
                    du += fabsf(unew - sU[ri]);
                    sU[ri] = unew; sA[ri] = a;
                }
                #pragma unroll
                for (int k = 0; k < 4; k++)
                    #pragma unroll
                    for (int e = 0; e < 8; e++)
                        Tacc[k][e] = fmaf(a, kf[k][e], Tacc[k][e]);
            }
        } else {
            // ---- steady state: fp16 K, double-buffered loads ----
            uint4 kq[4];
            {
                size_t qb = (size_t)wrow << 7;
                #pragma unroll
                for (int k = 0; k < 4; k++) kq[k] = K4[qb + (k << 5) + l];
            }
            for (int r = 0; r < RPW; r++) {
                uint4 kn[4];
                if (r + 1 < RPW) {
                    size_t qn = (size_t)(wrow + r + 1) << 7;
                    #pragma unroll
                    for (int k = 0; k < 4; k++) kn[k] = K4[qn + (k << 5) + l];
                }
                float kf[4][8];
                #pragma unroll
                for (int k = 0; k < 4; k++) h8_to_f8(kq[k], kf[k]);
                float s = 0.f;
                #pragma unroll
                for (int k = 0; k < 4; k++)
                    #pragma unroll
                    for (int e = 0; e < 8; e++) s = fmaf(kf[k][e], bb[k][e], s);
                #pragma unroll
                for (int o = 16; o; o >>= 1) s += __shfl_xor_sync(~0u, s, o);
                float a = MU / s;
                if (l == 0) {
                    float unew = EPS_F * (LOGM - logf(s));
                    int ri = w * RPW + r;
                    du += fabsf(unew - sU[ri]);
                    sU[ri] = unew; sA[ri] = a;
                }
                #pragma unroll
                for (int k = 0; k < 4; k++)
                    #pragma unroll
                    for (int e = 0; e < 8; e++)
                        Tacc[k][e] = fmaf(a, kf[k][e], Tacc[k][e]);
                if (r + 1 < RPW) {
                    #pragma unroll
                    for (int k = 0; k < 4; k++) kq[k] = kn[k];
                }
            }
        }

        // -------- block-combine 8 warps' column partials (deterministic) ----
        {
            float4* me = (float4*)sT[w];
            #pragma unroll
            for (int k = 0; k < 4; k++) {
                me[(((k << 5) + l) << 1)]     = make_float4(Tacc[k][0], Tacc[k][1], Tacc[k][2], Tacc[k][3]);
                me[(((k << 5) + l) << 1) + 1] = make_float4(Tacc[k][4], Tacc[k][5], Tacc[k][6], Tacc[k][7]);
            }
            if (l == 0) sred[w] = du;
        }
        __syncthreads();
        {
            float4 Tj = ((const float4*)sT[0])[tid];
            #pragma unroll
            for (int ww = 1; ww < 8; ww++) {
                float4 x = ((const float4*)sT[ww])[tid];
                Tj.x += x.x; Tj.y += x.y; Tj.z += x.z; Tj.w += x.w;
            }
            ((float4*)g_part[par][b][ib])[tid] = Tj;
        }
        if (tid == 0) {
            float e = 0.f;
            #pragma unroll
            for (int ww = 0; ww < 8; ww++) e += sred[ww];
            g_errpart[par][bid] = e;
        }

        // -------- barrier-shadow outC copy: one 16-row chunk per iteration --
        // Chunk c == warp c's rows (RPW == 16). Plain loads keep C L2-resident
        // for the epilogue's pi reads; __stcs writes drain while DRAM is idle.
        if (t >= 1 && copied < 8) {
            size_t base = ((size_t)(rowBase + (copied << 4) + (tid >> 4))) * 256
                        + (tid & 15);
            #pragma unroll
            for (int j = 0; j < 16; j++) {
                float4 v = C4[base + j * 16];
                __stcs(outC + base + j * 16, v);
            }
            copied++;
        }

        gridbar();

        // -------- v update: combine 8 block-partials (redundant per block) --
        float4 T = make_float4(0.f, 0.f, 0.f, 0.f);
        #pragma unroll
        for (int kk = 0; kk < PB; kk++) {
            float4 x = __ldcg(((const float4*)g_part[par][b][kk]) + tid);
            T.x += x.x; T.y += x.y; T.z += x.z; T.w += x.w;
        }
        float4 bbn;
        bbn.x = MU / T.x; bbn.y = MU / T.y; bbn.z = MU / T.z; bbn.w = MU / T.w;

        // deterministic err reduction
        sred[tid] = (tid < GRID) ? __ldcg(&g_errpart[par][tid]) : 0.f;
        __syncthreads();
        for (int o = 128; o; o >>= 1) {
            if (tid < o) sred[tid] += sred[tid + o];
            __syncthreads();
        }
        float err = sred[0];

        ((float4*)sb)[tid] = bbn;
        __syncthreads();

        if (err < 0.1f * (float)B) break;    // err/B < THRESH
        par ^= 1;
    }

    // ============= Epilogue: pi = a*b*exp(-C/eps), cost, remaining outC =====
    const float4* sb4 = (const float4*)sb;
    const bool doC = (w >= copied);          // warps whose chunk wasn't copied

    float cost = 0.f;
    for (int r = 0; r < RPW; r++) {
        int row = wrow + r;
        size_t f4 = (size_t)row << 8;
        float a = sA[w * RPW + r];
        #pragma unroll
        for (int k = 0; k < 8; k++) {
            int q = (k << 5) + l;
            float4 c  = C4[f4 + q];
            float4 bv = sb4[q];
            float4 p;
            p.x = a * bv.x * __expf(-c.x * INV_EPS);
            p.y = a * bv.y * __expf(-c.y * INV_EPS);
            p.z = a * bv.z * __expf(-c.z * INV_EPS);
            p.w = a * bv.w * __expf(-c.w * INV_EPS);
            outPi[f4 + q] = p;
            if (doC) outC[f4 + q] = c;
            cost += p.x * c.x + p.y * c.y + p.z * c.z + p.w * c.w;
        }
    }
    sred[tid] = cost;
    __syncthreads();
    for (int o = 128; o; o >>= 1) {
        if (tid < o) sred[tid] += sred[tid + o];
        __syncthreads();
    }
    if (tid == 0) g_costpart[bid] = sred[0];

    gridbar();

    if (bid == 0 && tid < B) {               // deterministic final cost sum
        float cs = 0.f;
        #pragma unroll
        for (int kk = 0; kk < PB; kk++)
            cs += __ldcg(&g_costpart[(tid << 3) + kk]);
        outCost[tid] = cs;
    }
}

// ---------------- launch -----------------------------------------------------
extern "C" void kernel_launch(void* const* d_in, const int* in_sizes, int n_in,
                              void* d_out, int out_size) {
    const float* C = nullptr;
    for (int i = 0; i < n_in; i++)
        if (in_sizes[i] == B * N * MP) C = (const float*)d_in[i];
    k_sinkhorn<<<GRID, TPB>>>(C, (float*)d_out);
    (void)out_size;
}